// round 7
// baseline (speedup 1.0000x reference)
#include <cuda_runtime.h>
#include <cstdint>

__device__ float g_lig_proj[512 * 512];
__device__ float g_rec_proj[512 * 512];
__device__ unsigned g_cnt[16];   // [0..7]=lig row-groups, [8..15]=rec row-groups (target 8 each)
__device__ unsigned g_done;

#define D 512
#define BM 64
#define BN 64
#define BK 16
#define NKT (D / BK)
#define NGEMM 128
#define NADD 2048
#define NTOT (NGEMM + NADD)

__device__ __forceinline__ uint32_t f2tf32(float x) {
    uint32_t r;
    asm("cvt.rna.tf32.f32 %0, %1;" : "=r"(r) : "f"(x));
    return r;
}

__device__ __forceinline__ void mma_tf32(float* d, const uint32_t* a, const uint32_t* b) {
    asm volatile(
        "mma.sync.aligned.m16n8k8.row.col.f32.tf32.tf32.f32 "
        "{%0,%1,%2,%3}, {%4,%5,%6,%7}, {%8,%9}, {%0,%1,%2,%3};"
        : "+f"(d[0]), "+f"(d[1]), "+f"(d[2]), "+f"(d[3])
        : "r"(a[0]), "r"(a[1]), "r"(a[2]), "r"(a[3]), "r"(b[0]), "r"(b[1]));
}

// Fused kernel. Blocks [0,128): tf32 tensor-core projection GEMM tiles (producer).
// Blocks [128, 2176): broadcast-add tiles (consumer), spin on row-group flags.
__global__ __launch_bounds__(256, 6) void fused_kernel(
    const float* __restrict__ lig,
    const float* __restrict__ rec,
    const float* __restrict__ W,
    const float* __restrict__ bias,
    float4* __restrict__ out)
{
    __shared__ uint32_t SaHi[2][BM * BK];
    __shared__ uint32_t SaLo[2][BM * BK];
    __shared__ uint32_t SbHi[2][BN * BK];
    __shared__ uint32_t SbLo[2][BN * BK];

    const int b = blockIdx.x;
    const int tid = threadIdx.x;

    if (b < NGEMM) {
        // ---------------- GEMM producer ----------------
        const int z = b >> 6;          // 0 = ligand, 1 = receptor
        const int rem = b & 63;
        const int by = rem >> 3;       // row-group 0..7
        const int bx = rem & 7;        // col-tile 0..7

        const float* A = (z == 0) ? lig : rec;
        float* C = (z == 0) ? g_lig_proj : g_rec_proj;
        const int w_off_f4 = (z == 0) ? 0 : (D / 4);

        const int lane = tid & 31;
        const int wid = tid >> 5;
        const int mwarp = wid >> 2;    // 0..1
        const int nwarp = wid & 3;     // 0..3
        const int i0 = by * BM;
        const int o0 = bx * BN;

        // Global load: 64 rows x 4 float4-cols = 256 float4 per matrix, 1 per thread.
        const int lr = tid >> 2;       // 0..63
        const int lcc = tid & 3;       // float4 col 0..3
        const float4* A4 = reinterpret_cast<const float4*>(A);
        const float4* W4 = reinterpret_cast<const float4*>(W);

        auto scatA = [&](int nb, float4 v) {
            #pragma unroll
            for (int q = 0; q < 4; q++) {
                float val = (q == 0) ? v.x : (q == 1) ? v.y : (q == 2) ? v.z : v.w;
                int k = lcc * 4 + q;                 // 0..15
                int mtile = lr >> 4, ktile = k >> 3;
                int rr = lr & 15, cc = k & 7;
                int ln = ((rr & 7) << 2) | (cc & 3);
                int idx = ((cc & 4) >> 1) | ((rr & 8) >> 3);
                int off = ((mtile * 2 + ktile) * 32 + ln) * 4 + idx;
                uint32_t hi = f2tf32(val);
                SaHi[nb][off] = hi;
                SaLo[nb][off] = f2tf32(val - __uint_as_float(hi));
            }
        };
        auto scatB = [&](int nb, float4 v) {
            #pragma unroll
            for (int q = 0; q < 4; q++) {
                float val = (q == 0) ? v.x : (q == 1) ? v.y : (q == 2) ? v.z : v.w;
                int k = lcc * 4 + q;
                int ntile = lr >> 3, ktile = k >> 3;
                int n = lr & 7, cc = k & 7;
                int ln = (n << 2) | (cc & 3);
                int idx = (cc & 4) >> 2;
                int off = ((ntile * 2 + ktile) * 32 + ln) * 2 + idx;
                uint32_t hi = f2tf32(val);
                SbHi[nb][off] = hi;
                SbLo[nb][off] = f2tf32(val - __uint_as_float(hi));
            }
        };

        float acc[2][2][4] = {};

        // Prologue: tile 0 into buffer 0
        {
            float4 va = A4[(size_t)(i0 + lr) * (D / 4) + lcc];
            float4 vb = W4[(size_t)(o0 + lr) * (2 * D / 4) + w_off_f4 + lcc];
            scatA(0, va); scatB(0, vb);
        }
        __syncthreads();

        int cur = 0;
        for (int t = 0; t < NKT; t++) {
            float4 na, nb_;
            if (t + 1 < NKT) {
                na  = A4[(size_t)(i0 + lr) * (D / 4) + (t + 1) * 4 + lcc];
                nb_ = W4[(size_t)(o0 + lr) * (2 * D / 4) + w_off_f4 + (t + 1) * 4 + lcc];
            }

            #pragma unroll
            for (int k8 = 0; k8 < 2; k8++) {
                uint32_t ahi[2][4], alo[2][4], bhi[2][2], blo[2][2];
                #pragma unroll
                for (int mt = 0; mt < 2; mt++) {
                    int base = (((mwarp * 2 + mt) * 2 + k8) * 32 + lane) * 4;
                    *reinterpret_cast<uint4*>(ahi[mt]) =
                        *reinterpret_cast<const uint4*>(&SaHi[cur][base]);
                    *reinterpret_cast<uint4*>(alo[mt]) =
                        *reinterpret_cast<const uint4*>(&SaLo[cur][base]);
                }
                #pragma unroll
                for (int nt = 0; nt < 2; nt++) {
                    int base = (((nwarp * 2 + nt) * 2 + k8) * 32 + lane) * 2;
                    *reinterpret_cast<uint2*>(bhi[nt]) =
                        *reinterpret_cast<const uint2*>(&SbHi[cur][base]);
                    *reinterpret_cast<uint2*>(blo[nt]) =
                        *reinterpret_cast<const uint2*>(&SbLo[cur][base]);
                }
                #pragma unroll
                for (int mt = 0; mt < 2; mt++)
                    #pragma unroll
                    for (int nt = 0; nt < 2; nt++) {
                        mma_tf32(acc[mt][nt], ahi[mt], bhi[nt]);
                        mma_tf32(acc[mt][nt], alo[mt], bhi[nt]);
                        mma_tf32(acc[mt][nt], ahi[mt], blo[nt]);
                    }
            }

            if (t + 1 < NKT) { scatA(cur ^ 1, na); scatB(cur ^ 1, nb_); }
            __syncthreads();
            cur ^= 1;
        }

        // Epilogue
        #pragma unroll
        for (int mt = 0; mt < 2; mt++) {
            #pragma unroll
            for (int nt = 0; nt < 2; nt++) {
                int row = i0 + mwarp * 32 + mt * 16 + (lane >> 2);
                int col = o0 + nwarp * 16 + nt * 8 + 2 * (lane & 3);
                float bv0 = 0.f, bv1 = 0.f;
                if (z == 1) { bv0 = bias[col]; bv1 = bias[col + 1]; }
                float2 lo_pair = make_float2(acc[mt][nt][0] + bv0, acc[mt][nt][1] + bv1);
                float2 hi_pair = make_float2(acc[mt][nt][2] + bv0, acc[mt][nt][3] + bv1);
                *reinterpret_cast<float2*>(&C[(size_t)row * D + col]) = lo_pair;
                *reinterpret_cast<float2*>(&C[(size_t)(row + 8) * D + col]) = hi_pair;
            }
        }

        __syncthreads();   // all C-tile stores happen-before the release below
        if (tid == 0) {
            unsigned* cp = &g_cnt[z * 8 + by];
            asm volatile("red.release.gpu.global.add.u32 [%0], %1;"
                         :: "l"(cp), "r"(1u) : "memory");
        }
    } else {
        // ---------------- broadcast-add consumer ----------------
        const int b2 = b - NGEMM;
        const int ib = b2 >> 5;        // 0..63, 8 i-rows each
        const int jb = b2 & 31;        // 0..31, 16 j-rows each
        const int gi = ib >> 3;        // lig group 0..7
        const int gj = jb >> 2;        // rec group 0..7

        if (tid == 0) {
            unsigned v;
            do {
                asm volatile("ld.acquire.gpu.global.u32 %0, [%1];"
                             : "=r"(v) : "l"(&g_cnt[gi]) : "memory");
                if (v < 8u) __nanosleep(64);
            } while (v < 8u);
            do {
                asm volatile("ld.acquire.gpu.global.u32 %0, [%1];"
                             : "=r"(v) : "l"(&g_cnt[8 + gj]) : "memory");
                if (v < 8u) __nanosleep(64);
            } while (v < 8u);
        }
        __syncthreads();

        const int c = tid & 127;       // float4 column
        const int h = tid >> 7;        // 0/1 -> i-subrange
        const int i0 = ib * 8 + h * 4;
        const int j0 = jb * 16;

        const float4* lig4 = reinterpret_cast<const float4*>(g_lig_proj);
        const float4* rec4 = reinterpret_cast<const float4*>(g_rec_proj);

        float4 a[4];
        #pragma unroll
        for (int u = 0; u < 4; u++)
            a[u] = lig4[(i0 + u) * 128 + c];

        const float4* rp = rec4 + (size_t)j0 * 128 + c;
        float4* op = out + ((size_t)i0 * D + j0) * 128 + c;

        for (int jj = 0; jj < 16; jj += 4) {
            float4 r[4];
            #pragma unroll
            for (int v = 0; v < 4; v++)
                r[v] = __ldg(rp + (size_t)(jj + v) * 128);
            #pragma unroll
            for (int v = 0; v < 4; v++) {
                #pragma unroll
                for (int u = 0; u < 4; u++) {
                    float4 o;
                    o.x = a[u].x + r[v].x;
                    o.y = a[u].y + r[v].y;
                    o.z = a[u].z + r[v].z;
                    o.w = a[u].w + r[v].w;
                    __stcs(op + ((size_t)u * D + jj + v) * 128, o);
                }
            }
        }
    }

    // ---- per-launch counter reset (last block out resets; deterministic across replays) ----
    if (tid == 0) {
        unsigned d = atomicAdd(&g_done, 1u);
        if (d == NTOT - 1) {
            #pragma unroll
            for (int q = 0; q < 16; q++) g_cnt[q] = 0u;
            __threadfence();
            g_done = 0u;
        }
    }
}

extern "C" void kernel_launch(void* const* d_in, const int* in_sizes, int n_in,
                              void* d_out, int out_size)
{
    const float* lig = (const float*)d_in[0];   // (512, 512)
    const float* rec = (const float*)d_in[1];   // (512, 512)
    const float* W   = (const float*)d_in[2];   // (512, 1024)
    const float* b   = (const float*)d_in[3];   // (512,)
    float4* out = (float4*)d_out;               // (512, 512, 512) f32

    fused_kernel<<<NTOT, 256>>>(lig, rec, W, b, out);
}

// round 8
// speedup vs baseline: 1.8514x; 1.8514x over previous
#include <cuda_runtime.h>
#include <cstdint>

__device__ float g_lig_proj[512 * 512];
__device__ float g_rec_proj[512 * 512];

#define D 512
#define BM 32
#define BN 64
#define BK 32
#define NKT (D / BK)
#define JBLK 64

__device__ __forceinline__ uint32_t f2tf32(float x) {
    uint32_t r;
    asm("cvt.rna.tf32.f32 %0, %1;" : "=r"(r) : "f"(x));
    return r;
}

__device__ __forceinline__ void mma_tf32(float* d, const uint32_t* a, const uint32_t* b) {
    asm volatile(
        "mma.sync.aligned.m16n8k8.row.col.f32.tf32.tf32.f32 "
        "{%0,%1,%2,%3}, {%4,%5,%6,%7}, {%8,%9}, {%0,%1,%2,%3};"
        : "+f"(d[0]), "+f"(d[1]), "+f"(d[2]), "+f"(d[3])
        : "r"(a[0]), "r"(a[1]), "r"(a[2]), "r"(a[3]), "r"(b[0]), "r"(b[1]));
}

// C[i,o] = sum_k A[i,k] * W[o, w_off + k] (+ bias for receptor).
// tf32 tensor cores, hi/lo compensation (3 MMAs per logical MMA), conversion at scatter time.
// Tile 32x64, BK=32, 256 threads, grid (8,16,2) = 256 blocks for latency hiding.
__global__ __launch_bounds__(256) void proj_gemm_kernel(
    const float* __restrict__ lig,
    const float* __restrict__ rec,
    const float* __restrict__ W,
    const float* __restrict__ bias)
{
    __shared__ uint32_t SaHi[BM * BK];   // [mtile(2)][ktile(4)][lane(32)][4]
    __shared__ uint32_t SaLo[BM * BK];
    __shared__ uint32_t SbHi[BN * BK];   // [ntile(8)][ktile(4)][lane(32)][2]
    __shared__ uint32_t SbLo[BN * BK];

    const int z = blockIdx.z;
    const float* A = (z == 0) ? lig : rec;
    float* C = (z == 0) ? g_lig_proj : g_rec_proj;
    const int w_off_f4 = (z == 0) ? 0 : (D / 4);

    const int tid = threadIdx.x;
    const int lane = tid & 31;
    const int wid = tid >> 5;
    const int mwarp = wid >> 2;     // 0..1 -> which m16 tile
    const int nwarp = wid & 3;      // 0..3 -> 16 cols each
    const int i0 = blockIdx.y * BM;
    const int o0 = blockIdx.x * BN;

    // A tile: 32 rows x 8 f4-cols = 256 float4 (1/thread). W tile: 64 rows x 8 = 512 (2/thread).
    const int lr = tid >> 3;        // 0..31
    const int lc = tid & 7;         // f4 col 0..7
    const float4* A4 = reinterpret_cast<const float4*>(A);
    const float4* W4 = reinterpret_cast<const float4*>(W);

    float acc[2][4] = {};           // [nt][quad] — each warp owns m16 x n16

    auto scatA = [&](float4 v) {
        #pragma unroll
        for (int q = 0; q < 4; q++) {
            float val = (q == 0) ? v.x : (q == 1) ? v.y : (q == 2) ? v.z : v.w;
            int kl = lc * 4 + q;
            int mtile = lr >> 4, ktile = kl >> 3;
            int rr = lr & 15, cc = kl & 7;
            int ln = ((rr & 7) << 2) | (cc & 3);
            int idx = ((cc & 4) >> 1) | ((rr & 8) >> 3);
            int off = ((mtile * 4 + ktile) * 32 + ln) * 4 + idx;
            uint32_t hi = f2tf32(val);
            SaHi[off] = hi;
            SaLo[off] = f2tf32(val - __uint_as_float(hi));
        }
    };
    auto scatB = [&](int r, float4 v) {
        #pragma unroll
        for (int q = 0; q < 4; q++) {
            float val = (q == 0) ? v.x : (q == 1) ? v.y : (q == 2) ? v.z : v.w;
            int kl = lc * 4 + q;
            int ntile = r >> 3, ktile = kl >> 3;
            int n = r & 7, cc = kl & 7;
            int ln = (n << 2) | (cc & 3);
            int idx = (cc & 4) >> 2;
            int off = ((ntile * 4 + ktile) * 32 + ln) * 2 + idx;
            uint32_t hi = f2tf32(val);
            SbHi[off] = hi;
            SbLo[off] = f2tf32(val - __uint_as_float(hi));
        }
    };

    // Prologue: tile 0
    {
        float4 va  = A4[(size_t)(i0 + lr) * (D / 4) + lc];
        float4 vb0 = W4[(size_t)(o0 + lr)      * (2 * D / 4) + w_off_f4 + lc];
        float4 vb1 = W4[(size_t)(o0 + lr + 32) * (2 * D / 4) + w_off_f4 + lc];
        scatA(va); scatB(lr, vb0); scatB(lr + 32, vb1);
    }
    __syncthreads();

    for (int t = 0; t < NKT; t++) {
        float4 va, vb0, vb1;
        if (t + 1 < NKT) {
            const int kc4 = (t + 1) * (BK / 4);
            va  = A4[(size_t)(i0 + lr) * (D / 4) + kc4 + lc];
            vb0 = W4[(size_t)(o0 + lr)      * (2 * D / 4) + w_off_f4 + kc4 + lc];
            vb1 = W4[(size_t)(o0 + lr + 32) * (2 * D / 4) + w_off_f4 + kc4 + lc];
        }

        #pragma unroll
        for (int k8 = 0; k8 < 4; k8++) {
            uint32_t ahi[4], alo[4], bhi[2][2], blo[2][2];
            {
                int base = ((mwarp * 4 + k8) * 32 + lane) * 4;
                *reinterpret_cast<uint4*>(ahi) = *reinterpret_cast<const uint4*>(&SaHi[base]);
                *reinterpret_cast<uint4*>(alo) = *reinterpret_cast<const uint4*>(&SaLo[base]);
            }
            #pragma unroll
            for (int nt = 0; nt < 2; nt++) {
                int base = (((nwarp * 2 + nt) * 4 + k8) * 32 + lane) * 2;
                *reinterpret_cast<uint2*>(bhi[nt]) = *reinterpret_cast<const uint2*>(&SbHi[base]);
                *reinterpret_cast<uint2*>(blo[nt]) = *reinterpret_cast<const uint2*>(&SbLo[base]);
            }
            #pragma unroll
            for (int nt = 0; nt < 2; nt++) {
                mma_tf32(acc[nt], ahi, bhi[nt]);
                mma_tf32(acc[nt], alo, bhi[nt]);
                mma_tf32(acc[nt], ahi, blo[nt]);
            }
        }

        __syncthreads();
        if (t + 1 < NKT) {
            scatA(va); scatB(lr, vb0); scatB(lr + 32, vb1);
            __syncthreads();
        }
    }

    // Epilogue
    #pragma unroll
    for (int nt = 0; nt < 2; nt++) {
        int row = i0 + mwarp * 16 + (lane >> 2);
        int col = o0 + nwarp * 16 + nt * 8 + 2 * (lane & 3);
        float bv0 = 0.f, bv1 = 0.f;
        if (z == 1) { bv0 = bias[col]; bv1 = bias[col + 1]; }
        float2 lo_pair = make_float2(acc[nt][0] + bv0, acc[nt][1] + bv1);
        float2 hi_pair = make_float2(acc[nt][2] + bv0, acc[nt][3] + bv1);
        *reinterpret_cast<float2*>(&C[(size_t)row * D + col]) = lo_pair;
        *reinterpret_cast<float2*>(&C[(size_t)(row + 8) * D + col]) = hi_pair;
    }
}

// out[i, j, :] = lig_proj[i, :] + rec_proj[j, :]
// R2 configuration (best measured): block = (1 i, 64 j), 128 threads, 4096 blocks.
__global__ __launch_bounds__(128) void pair_add_kernel(float4* __restrict__ out)
{
    const int c = threadIdx.x;            // float4 column 0..127
    const int i = blockIdx.y;
    const int j0 = blockIdx.x * JBLK;

    const float4* lig = reinterpret_cast<const float4*>(g_lig_proj);
    const float4* rec = reinterpret_cast<const float4*>(g_rec_proj);

    const float4 a = lig[i * 128 + c];

    const float4* rp = rec + (size_t)j0 * 128 + c;
    float4* op = out + ((size_t)i * D + j0) * 128 + c;

    #pragma unroll 8
    for (int jj = 0; jj < JBLK; jj++) {
        float4 r = __ldg(rp + (size_t)jj * 128);
        float4 o;
        o.x = a.x + r.x;
        o.y = a.y + r.y;
        o.z = a.z + r.z;
        o.w = a.w + r.w;
        __stcs(op + (size_t)jj * 128, o);
    }
}

extern "C" void kernel_launch(void* const* d_in, const int* in_sizes, int n_in,
                              void* d_out, int out_size)
{
    const float* lig = (const float*)d_in[0];   // (512, 512)
    const float* rec = (const float*)d_in[1];   // (512, 512)
    const float* W   = (const float*)d_in[2];   // (512, 1024)
    const float* b   = (const float*)d_in[3];   // (512,)
    float* out = (float*)d_out;                 // (512, 512, 512)

    dim3 ggrd(D / BN, D / BM, 2);   // 8 x 16 x 2 = 256 blocks
    proj_gemm_kernel<<<ggrd, 256>>>(lig, rec, W, b);

    dim3 agrd(D / JBLK, D);         // 8 x 512 = 4096 blocks
    pair_add_kernel<<<agrd, 128>>>(reinterpret_cast<float4*>(out));
}